// round 5
// baseline (speedup 1.0000x reference)
#include <cuda_runtime.h>
#include <math.h>

#define BB 16
#define AA 3
#define SDIM 80
#define NC 80
#define NT 32
#define SSP (SDIM * SDIM)             // 6400
#define CH (5 + NC)                   // 85
#define CELLS (BB * AA * SSP)         // 307200
#define NTARG (BB * NT)               // 512
#define NTHR 128
#define F4_PER_THR 4
#define CONF_BLK (CELLS / 4 / (NTHR * F4_PER_THR))   // 150
#define TOT_BLK (CONF_BLK + NTARG)                   // 662
#define OBJ_STRIDE 8
#define EPSF 1e-7f
#define IMG 640.0f
#define STRIDEF 8.0f

// Scratch: every word rewritten each call; counter self-resets to 0.
__device__ float        g_confpart[CONF_BLK];
__device__ float        g_objout[NTARG * OBJ_STRIDE];
__device__ unsigned int g_arrived = 0;

__device__ __forceinline__ float softplusf(float x) {
    return fmaxf(x, 0.0f) + log1pf(__expf(-fabsf(x)));
}
__device__ __forceinline__ float sigmoidf(float x) {
    return 1.0f / (1.0f + __expf(-x));
}

// 128-thread block sum; result valid in thread 0; ends synced.
__device__ __forceinline__ float block_sum128(float v, volatile float* red, int tid) {
    #pragma unroll
    for (int o = 16; o > 0; o >>= 1) v += __shfl_down_sync(0xffffffffu, v, o);
    if ((tid & 31) == 0) red[tid >> 5] = v;
    __syncthreads();
    if (tid == 0) v = red[0] + red[1] + red[2] + red[3];
    __syncthreads();
    return v;
}

__device__ __forceinline__ void assign_target(
    const float* __restrict__ tbox, const float* aw, const float* ah,
    int b, int m, int& a, int& gi, int& gj)
{
    const float* p = tbox + (size_t)(b * NT + m) * 4;
    float x = p[0], y = p[1], w = p[2], h = p[3];
    gi = min(max((int)floorf(x * (float)SDIM), 0), SDIM - 1);
    gj = min(max((int)floorf(y * (float)SDIM), 0), SDIM - 1);
    float tw = w * IMG, th = h * IMG;
    float best = -1.0f; a = 0;
    #pragma unroll
    for (int k = 0; k < AA; k++) {
        float inter = fminf(tw, aw[k]) * fminf(th, ah[k]);
        float un = tw * th + aw[k] * ah[k] - inter;
        float r = inter / un;
        if (r > best) { best = r; a = k; }   // first-max wins (jnp.argmax)
    }
}

__device__ __forceinline__ float ciou_f(
    float px1, float py1, float px2, float py2,
    float tx1, float ty1, float tx2, float ty2)
{
    float iw = fmaxf(fminf(px2, tx2) - fmaxf(px1, tx1), 0.0f);
    float ih = fmaxf(fminf(py2, ty2) - fmaxf(py1, ty1), 0.0f);
    float inter = iw * ih;
    float pa = fmaxf(px2 - px1, 0.0f) * fmaxf(py2 - py1, 0.0f);
    float ta = fmaxf(tx2 - tx1, 0.0f) * fmaxf(ty2 - ty1, 0.0f);
    float un = pa + ta - inter + EPSF;
    float iou = inter / un;
    float dx = 0.5f * (px1 + px2) - 0.5f * (tx1 + tx2);
    float dy = 0.5f * (py1 + py2) - 0.5f * (ty1 + ty2);
    float cd = dx * dx + dy * dy;
    float ew = fmaxf(px2, tx2) - fminf(px1, tx1);
    float eh = fmaxf(py2, ty2) - fminf(py1, ty1);
    float ed = ew * ew + eh * eh + EPSF;
    float pw = fmaxf(px2 - px1, EPSF);
    float ph = fmaxf(py2 - py1, EPSF);
    float tw = fmaxf(tx2 - tx1, EPSF);
    float th = fmaxf(ty2 - ty1, EPSF);
    float da = atanf(tw / th) - atanf(pw / ph);
    float v = (4.0f / ((float)M_PI * (float)M_PI)) * da * da;
    float alpha = v / (1.0f - iou + v + EPSF);
    return iou - cd / ed - alpha * v;
}

__global__ void __launch_bounds__(NTHR)
yolo_all(const float* __restrict__ preds,
         const float* __restrict__ anchors,
         const int* __restrict__ tcls,
         const float* __restrict__ tbox,
         float* __restrict__ out)
{
    __shared__ float    red[4];
    __shared__ int      s_cell[NT];
    __shared__ int      s_cls[NT];
    __shared__ unsigned s_bits[3];
    __shared__ int      s_lastm;
    __shared__ int      s_islast;

    int tid = threadIdx.x;
    int blk = blockIdx.x;

    if (blk < CONF_BLK) {
        // ── conf phase: 4 independent float4 loads per thread (MLP=4) ──
        float s = 0.0f;
        #pragma unroll
        for (int k = 0; k < F4_PER_THR; k++) {
            int idx = blk * (NTHR * F4_PER_THR) + k * NTHR + tid; // f4 index
            int plane = idx / (SSP / 4);          // b*3 + a
            int off4  = idx - plane * (SSP / 4);
            int b = plane / AA, a = plane - AA * b;
            const float4* p4 = (const float4*)(preds +
                ((size_t)(b * (AA * CH) + a * CH + 4)) * SSP);
            float4 v = p4[off4];
            s += softplusf(v.x) + softplusf(v.y) + softplusf(v.z) + softplusf(v.w);
        }
        float bsum = block_sum128(s, red, tid);
        if (tid == 0) g_confpart[blk] = bsum;
    } else {
        // ── obj phase: one block per target ──
        int t = blk - CONF_BLK;                    // 0..511
        int b = t / NT, n = t - b * NT;

        float aw[AA], ah[AA];
        #pragma unroll
        for (int k = 0; k < AA; k++) { aw[k] = anchors[2*k]; ah[k] = anchors[2*k+1]; }

        if (tid < NT) {
            int a, gi, gj;
            assign_target(tbox, aw, ah, b, tid, a, gi, gj);
            s_cell[tid] = ((b * AA + a) * SDIM + gj) * SDIM + gi;
            s_cls[tid]  = tcls[b * NT + tid];
        }
        if (tid == 0) { s_bits[0] = s_bits[1] = s_bits[2] = 0u; s_lastm = -1; }
        __syncthreads();

        int cell = s_cell[n];
        bool owner = true;                          // block-uniform
        for (int m = 0; m < n; m++)
            if (s_cell[m] == cell) { owner = false; break; }

        float* slot = g_objout + (size_t)t * OBJ_STRIDE;
        if (owner) {
            if (tid < NT && s_cell[tid] == cell) {
                int c = s_cls[tid];
                atomicOr(&s_bits[c >> 5], 1u << (c & 31));
                atomicMax(&s_lastm, tid);
            }
            __syncthreads();

            int gi = cell % SDIM;
            int gj = (cell / SDIM) % SDIM;
            int a  = (cell / SSP) % AA;
            size_t base = ((size_t)b * (AA * CH) + (size_t)a * CH) * SSP
                          + (size_t)gj * SDIM + gi;

            float cs = 0.0f;
            if (tid < NC) {
                float l = preds[base + (size_t)(5 + tid) * SSP];
                float tgt = (float)((s_bits[tid >> 5] >> (tid & 31)) & 1u);
                cs = softplusf(l) - l * tgt;
            }
            float cls_sum = block_sum128(cs, red, tid);

            if (tid == 0) {
                float p0 = preds[base];
                float p1 = preds[base + (size_t)SSP];
                float p2 = preds[base + (size_t)2 * SSP];
                float p3 = preds[base + (size_t)3 * SSP];
                float pc = preds[base + (size_t)4 * SSP];

                const float* tp = tbox + (size_t)(b * NT + s_lastm) * 4;
                float cx = tp[0] * IMG, cy = tp[1] * IMG;
                float tw = tp[2] * IMG, th = tp[3] * IMG;

                float pcx = (sigmoidf(p0) + (float)gi) * STRIDEF;
                float pcy = (sigmoidf(p1) + (float)gj) * STRIDEF;
                float pw = aw[a] * __expf(p2);
                float ph = ah[a] * __expf(p3);

                float ciou = ciou_f(pcx - 0.5f*pw, pcy - 0.5f*ph,
                                    pcx + 0.5f*pw, pcy + 0.5f*ph,
                                    cx - 0.5f*tw, cy - 0.5f*th,
                                    cx + 0.5f*tw, cy + 0.5f*th);
                float sp = softplusf(pc);
                slot[0] = 1.0f;
                slot[1] = ciou;
                slot[2] = sp - pc;
                slot[3] = sp;
                slot[4] = cls_sum;
            }
        } else {
            if (tid == 0) {
                slot[0] = 0.f; slot[1] = 0.f; slot[2] = 0.f;
                slot[3] = 0.f; slot[4] = 0.f;
            }
        }
    }

    // ── grid-wide handshake (threadFenceReduction pattern) ──
    __threadfence();
    if (tid == 0) {
        unsigned old = atomicAdd(&g_arrived, 1u);
        s_islast = (old == (unsigned)(TOT_BLK - 1));
    }
    __syncthreads();
    if (!s_islast) return;

    // ── finalize (last block only; light work) ──
    float conf = 0.f;
    for (int i = tid; i < CONF_BLK; i += NTHR) conf += g_confpart[i];

    float cnt = 0.f, ciou = 0.f, bce = 0.f, sp = 0.f, cls = 0.f;
    const float4* po = (const float4*)g_objout;
    for (int j = tid; j < NTARG; j += NTHR) {
        float4 u0 = po[j * 2];
        float4 u1 = po[j * 2 + 1];
        cnt += u0.x; ciou += u0.y; bce += u0.z; sp += u0.w; cls += u1.x;
    }

    float r_conf = block_sum128(conf, red, tid);
    float r_cnt  = block_sum128(cnt,  red, tid);
    float r_ciou = block_sum128(ciou, red, tid);
    float r_bce  = block_sum128(bce,  red, tid);
    float r_sp   = block_sum128(sp,   red, tid);
    float r_cls  = block_sum128(cls,  red, tid);

    if (tid == 0) {
        double nobj = (double)r_cnt;
        double dn_obj   = fmax(nobj, 1.0);
        double dn_noobj = fmax((double)CELLS - nobj, 1.0);
        double dn_cls   = fmax(nobj * (double)NC, 1.0);

        double loss_ciou       = 1.0 - (double)r_ciou / dn_obj;
        double loss_conf_obj   = (double)r_bce / dn_obj;
        double loss_conf_noobj = ((double)r_conf - (double)r_sp) / dn_noobj;
        double loss_cls        = (double)r_cls / dn_cls;

        out[0] = (float)(loss_ciou + loss_conf_obj
                         + 0.5 * loss_conf_noobj + loss_cls);

        g_arrived = 0u;   // self-reset for next graph replay
    }
}

extern "C" void kernel_launch(void* const* d_in, const int* in_sizes, int n_in,
                              void* d_out, int out_size)
{
    const float* preds   = (const float*)d_in[0];
    const float* anchors = (const float*)d_in[1];
    const int*   tcls    = (const int*)d_in[2];
    const float* tbox    = (const float*)d_in[3];

    yolo_all<<<TOT_BLK, NTHR>>>(preds, anchors, tcls, tbox, (float*)d_out);
}

// round 6
// speedup vs baseline: 1.0226x; 1.0226x over previous
#include <cuda_runtime.h>
#include <math.h>

#define BB 16
#define AA 3
#define SDIM 80
#define NC 80
#define NT 32
#define SSP (SDIM * SDIM)             // 6400
#define CH (5 + NC)                   // 85
#define CELLS (BB * AA * SSP)         // 307200
#define NTARG (BB * NT)               // 512
#define NTHR 128
#define F4_PER_THR 4
#define CONF_BLK (CELLS / 4 / (NTHR * F4_PER_THR))   // 150
#define TOT_BLK (CONF_BLK + NTARG)                   // 662
#define OBJ_STRIDE 8
#define EPSF 1e-7f
#define IMG 640.0f
#define STRIDEF 8.0f

// Scratch: every word rewritten by plain stores each call. No handshake state.
__device__ float g_confpart[CONF_BLK];
__device__ float g_objout[NTARG * OBJ_STRIDE];

__device__ __forceinline__ float softplusf(float x) {
    return fmaxf(x, 0.0f) + log1pf(__expf(-fabsf(x)));
}
__device__ __forceinline__ float sigmoidf(float x) {
    return 1.0f / (1.0f + __expf(-x));
}

__device__ __forceinline__ float ciou_f(
    float px1, float py1, float px2, float py2,
    float tx1, float ty1, float tx2, float ty2)
{
    float iw = fmaxf(fminf(px2, tx2) - fmaxf(px1, tx1), 0.0f);
    float ih = fmaxf(fminf(py2, ty2) - fmaxf(py1, ty1), 0.0f);
    float inter = iw * ih;
    float pa = fmaxf(px2 - px1, 0.0f) * fmaxf(py2 - py1, 0.0f);
    float ta = fmaxf(tx2 - tx1, 0.0f) * fmaxf(ty2 - ty1, 0.0f);
    float un = pa + ta - inter + EPSF;
    float iou = inter / un;
    float dx = 0.5f * (px1 + px2) - 0.5f * (tx1 + tx2);
    float dy = 0.5f * (py1 + py2) - 0.5f * (ty1 + ty2);
    float cd = dx * dx + dy * dy;
    float ew = fmaxf(px2, tx2) - fminf(px1, tx1);
    float eh = fmaxf(py2, ty2) - fminf(py1, ty1);
    float ed = ew * ew + eh * eh + EPSF;
    float pw = fmaxf(px2 - px1, EPSF);
    float ph = fmaxf(py2 - py1, EPSF);
    float tw = fmaxf(tx2 - tx1, EPSF);
    float th = fmaxf(ty2 - ty1, EPSF);
    float da = atanf(tw / th) - atanf(pw / ph);
    float v = (4.0f / ((float)M_PI * (float)M_PI)) * da * da;
    float alpha = v / (1.0f - iou + v + EPSF);
    return iou - cd / ed - alpha * v;
}

// ── Kernel A: conf partials (blocks 0..149) + per-target obj (blocks 150..661)
__global__ void __launch_bounds__(NTHR)
k_work(const float* __restrict__ preds,
       const float* __restrict__ anchors,
       const int* __restrict__ tcls,
       const float* __restrict__ tbox)
{
    __shared__ float    red[4];
    int tid = threadIdx.x;
    int blk = blockIdx.x;

    if (blk < CONF_BLK) {
        // conf: 4 independent float4 loads per thread (MLP=4, one round-trip)
        float s = 0.0f;
        #pragma unroll
        for (int k = 0; k < F4_PER_THR; k++) {
            int idx = blk * (NTHR * F4_PER_THR) + k * NTHR + tid;
            int plane = idx / (SSP / 4);
            int off4  = idx - plane * (SSP / 4);
            int b = plane / AA, a = plane - AA * b;
            const float4* p4 = (const float4*)(preds +
                ((size_t)(b * (AA * CH) + a * CH + 4)) * SSP);
            float4 v = p4[off4];
            s += softplusf(v.x) + softplusf(v.y) + softplusf(v.z) + softplusf(v.w);
        }
        #pragma unroll
        for (int o = 16; o > 0; o >>= 1) s += __shfl_down_sync(0xffffffffu, s, o);
        if ((tid & 31) == 0) red[tid >> 5] = s;
        __syncthreads();
        if (tid == 0) g_confpart[blk] = red[0] + red[1] + red[2] + red[3];
        return;
    }

    // ── obj block: 2 dependent memory round-trips total ──
    __shared__ float4   s_tbox[NT];
    __shared__ int      s_cls[NT];
    __shared__ float    s_anch[2 * AA];
    __shared__ int      s_cell[NT];
    __shared__ unsigned s_bits[3];
    __shared__ int      s_lastm;
    __shared__ float    s_pred[5];

    int t = blk - CONF_BLK;            // 0..511
    int b = t / NT, n = t - b * NT;

    // round-trip 1: all small inputs in parallel
    if (tid < NT) {
        s_tbox[tid] = ((const float4*)tbox)[b * NT + tid];
        s_cls[tid]  = tcls[b * NT + tid];
    } else if (tid >= 64 && tid < 64 + 2 * AA) {
        s_anch[tid - 64] = anchors[tid - 64];
    }
    if (tid == 0) { s_bits[0] = s_bits[1] = s_bits[2] = 0u; s_lastm = -1; }
    __syncthreads();

    // ALU-only: assignments for all 32 targets of this batch
    if (tid < NT) {
        float4 tb = s_tbox[tid];
        int gi = min(max((int)floorf(tb.x * (float)SDIM), 0), SDIM - 1);
        int gj = min(max((int)floorf(tb.y * (float)SDIM), 0), SDIM - 1);
        float tw = tb.z * IMG, th = tb.w * IMG;
        float best = -1.0f; int a = 0;
        #pragma unroll
        for (int k = 0; k < AA; k++) {
            float awk = s_anch[2 * k], ahk = s_anch[2 * k + 1];
            float inter = fminf(tw, awk) * fminf(th, ahk);
            float un = tw * th + awk * ahk - inter;
            float r = inter / un;
            if (r > best) { best = r; a = k; }   // first-max wins
        }
        s_cell[tid] = ((b * AA + a) * SDIM + gj) * SDIM + gi;
    }
    __syncthreads();

    int cell = s_cell[n];
    bool owner = true;                  // block-uniform result
    for (int m = 0; m < n; m++)
        if (s_cell[m] == cell) { owner = false; break; }

    float* slot = g_objout + (size_t)t * OBJ_STRIDE;
    if (!owner) {
        if (tid == 0) {
            slot[0] = 0.f; slot[1] = 0.f; slot[2] = 0.f; slot[3] = 0.f; slot[4] = 0.f;
        }
        return;
    }

    // decode cell, compute base (ALU)
    int gi = cell % SDIM;
    int gj = (cell / SDIM) % SDIM;
    int a  = (cell / SSP) % AA;
    size_t base = ((size_t)b * (AA * CH) + (size_t)a * CH) * SSP
                  + (size_t)gj * SDIM + gi;

    // round-trip 2: 80 class logits + 5 box/conf preds, ALL in parallel.
    float l = 0.0f;
    if (tid < NC) {
        l = preds[base + (size_t)(5 + tid) * SSP];
    } else if (tid >= 96 && tid < 101) {
        s_pred[tid - 96] = preds[base + (size_t)(tid - 96) * SSP];
    }
    // class-set union + last-write-wins (overlaps with the loads above)
    if (tid < NT && s_cell[tid] == cell) {
        int c = s_cls[tid];
        atomicOr(&s_bits[c >> 5], 1u << (c & 31));
        atomicMax(&s_lastm, tid);
    }
    __syncthreads();

    float cs = 0.0f;
    if (tid < NC) {
        float tgt = (float)((s_bits[tid >> 5] >> (tid & 31)) & 1u);
        cs = softplusf(l) - l * tgt;
    }
    #pragma unroll
    for (int o = 16; o > 0; o >>= 1) cs += __shfl_down_sync(0xffffffffu, cs, o);
    if ((tid & 31) == 0) red[tid >> 5] = cs;
    __syncthreads();

    if (tid == 0) {
        float cls_sum = red[0] + red[1] + red[2] + red[3];

        float4 tb = s_tbox[s_lastm];
        float cx = tb.x * IMG, cy = tb.y * IMG;
        float tw = tb.z * IMG, th = tb.w * IMG;

        float pcx = (sigmoidf(s_pred[0]) + (float)gi) * STRIDEF;
        float pcy = (sigmoidf(s_pred[1]) + (float)gj) * STRIDEF;
        float pw = s_anch[2 * a]     * __expf(s_pred[2]);
        float ph = s_anch[2 * a + 1] * __expf(s_pred[3]);
        float pc = s_pred[4];

        float ciou = ciou_f(pcx - 0.5f * pw, pcy - 0.5f * ph,
                            pcx + 0.5f * pw, pcy + 0.5f * ph,
                            cx - 0.5f * tw, cy - 0.5f * th,
                            cx + 0.5f * tw, cy + 0.5f * th);
        float sp = softplusf(pc);

        slot[0] = 1.0f;
        slot[1] = ciou;
        slot[2] = sp - pc;
        slot[3] = sp;
        slot[4] = cls_sum;
    }
}

// ── Kernel B: light finalize (1 block, ~12 KB of L2 reads) ─────────────────
__global__ void __launch_bounds__(256)
k_final(float* __restrict__ out)
{
    __shared__ float red[8];
    int tid = threadIdx.x;

    float conf = (tid < CONF_BLK) ? g_confpart[tid] : 0.0f;

    float cnt = 0.f, ciou = 0.f, bce = 0.f, sp = 0.f, cls = 0.f;
    const float4* po = (const float4*)g_objout;
    #pragma unroll
    for (int k = 0; k < NTARG / 256; k++) {
        int j = k * 256 + tid;
        float4 u0 = po[j * 2];
        float4 u1 = po[j * 2 + 1];
        cnt += u0.x; ciou += u0.y; bce += u0.z; sp += u0.w; cls += u1.x;
    }

    float vals[6] = { conf, cnt, ciou, bce, sp, cls };
    float sums[6];
    #pragma unroll
    for (int i = 0; i < 6; i++) {
        float v = vals[i];
        #pragma unroll
        for (int o = 16; o > 0; o >>= 1) v += __shfl_down_sync(0xffffffffu, v, o);
        if ((tid & 31) == 0) red[tid >> 5] = v;
        __syncthreads();
        if (tid == 0) {
            v = 0.f;
            #pragma unroll
            for (int w = 0; w < 8; w++) v += red[w];
        }
        __syncthreads();
        sums[i] = v;
    }

    if (tid == 0) {
        double nobj = (double)sums[1];
        double dn_obj   = fmax(nobj, 1.0);
        double dn_noobj = fmax((double)CELLS - nobj, 1.0);
        double dn_cls   = fmax(nobj * (double)NC, 1.0);

        double loss_ciou       = 1.0 - (double)sums[2] / dn_obj;
        double loss_conf_obj   = (double)sums[3] / dn_obj;
        double loss_conf_noobj = ((double)sums[0] - (double)sums[4]) / dn_noobj;
        double loss_cls        = (double)sums[5] / dn_cls;

        out[0] = (float)(loss_ciou + loss_conf_obj
                         + 0.5 * loss_conf_noobj + loss_cls);
    }
}

extern "C" void kernel_launch(void* const* d_in, const int* in_sizes, int n_in,
                              void* d_out, int out_size)
{
    const float* preds   = (const float*)d_in[0];
    const float* anchors = (const float*)d_in[1];
    const int*   tcls    = (const int*)d_in[2];
    const float* tbox    = (const float*)d_in[3];

    k_work<<<TOT_BLK, NTHR>>>(preds, anchors, tcls, tbox);
    k_final<<<1, 256>>>((float*)d_out);
}